// round 1
// baseline (speedup 1.0000x reference)
#include <cuda_runtime.h>
#include <math.h>

#define BB   4
#define SS_  1024
#define HIDD 1024
#define NH   16
#define NKH  8
#define HD   64
#define TOKENS (BB * SS_)   // 4096

// ---------------- scratch (no allocations allowed) ----------------
__device__ float g_qkv[(size_t)TOKENS * 2048];          // [token][0:1024 q | 1024:1536 k | 1536:2048 v]
__device__ float g_q[(size_t)BB * NH  * SS_ * HD];      // [b][h][s][d]
__device__ float g_k[(size_t)BB * NKH * SS_ * HD];
__device__ float g_v[(size_t)BB * NKH * SS_ * HD];
__device__ float g_ao[(size_t)TOKENS * NH * HD];        // [b*s][h*64+d]

// ---------------- generic tiled SGEMM: C[M,N] = A[M,K] @ B[K,N] ----------------
// BM=BN=128, BK=8, 256 threads, 8x8 per thread. All dims divisible, no bounds checks.
__global__ __launch_bounds__(256)
void sgemm128(const float* __restrict__ A, const float* __restrict__ Bm,
              float* __restrict__ C, int K, int lda, int ldb, int ldc)
{
    __shared__ float As[8][128];
    __shared__ float Bs[8][128];

    const int tid = threadIdx.x;
    const int tx  = tid & 15;
    const int ty  = tid >> 4;

    A  += (size_t)(blockIdx.y * 128) * lda;
    Bm += blockIdx.x * 128;
    C  += (size_t)(blockIdx.y * 128) * ldc + blockIdx.x * 128;

    const int aRow = tid >> 1;            // 0..127
    const int aCol = (tid & 1) * 4;       // 0 or 4
    const int bRow = tid >> 5;            // 0..7
    const int bCol = (tid & 31) * 4;      // 0..124

    float acc[8][8];
#pragma unroll
    for (int i = 0; i < 8; ++i)
#pragma unroll
        for (int j = 0; j < 8; ++j) acc[i][j] = 0.f;

    for (int k0 = 0; k0 < K; k0 += 8) {
        float4 av = *(const float4*)(A + (size_t)aRow * lda + k0 + aCol);
        float4 bv = *(const float4*)(Bm + (size_t)(k0 + bRow) * ldb + bCol);
        As[aCol + 0][aRow] = av.x;
        As[aCol + 1][aRow] = av.y;
        As[aCol + 2][aRow] = av.z;
        As[aCol + 3][aRow] = av.w;
        *(float4*)&Bs[bRow][bCol] = bv;
        __syncthreads();

#pragma unroll
        for (int kk = 0; kk < 8; ++kk) {
            float ra[8], rb[8];
            *(float4*)&ra[0] = *(const float4*)&As[kk][ty * 8];
            *(float4*)&ra[4] = *(const float4*)&As[kk][ty * 8 + 4];
            *(float4*)&rb[0] = *(const float4*)&Bs[kk][tx * 8];
            *(float4*)&rb[4] = *(const float4*)&Bs[kk][tx * 8 + 4];
#pragma unroll
            for (int i = 0; i < 8; ++i)
#pragma unroll
                for (int j = 0; j < 8; ++j)
                    acc[i][j] = fmaf(ra[i], rb[j], acc[i][j]);
        }
        __syncthreads();
    }

#pragma unroll
    for (int i = 0; i < 8; ++i) {
        float* crow = C + (size_t)(ty * 8 + i) * ldc + tx * 8;
        *(float4*)(crow + 0) = make_float4(acc[i][0], acc[i][1], acc[i][2], acc[i][3]);
        *(float4*)(crow + 4) = make_float4(acc[i][4], acc[i][5], acc[i][6], acc[i][7]);
    }
}

// ---------------- RMSNorm + 2D RoPE epilogue ----------------
// One warp per (token, head-row). 32 rows/token: 16 q + 8 k + 8 v.
__global__ __launch_bounds__(256)
void qkv_epilogue(const float* __restrict__ qkv,
                  const float* __restrict__ qg, const float* __restrict__ kg,
                  const int* __restrict__ pos,
                  float* __restrict__ q, float* __restrict__ k, float* __restrict__ v)
{
    const int w     = (blockIdx.x * blockDim.x + threadIdx.x) >> 5;
    const int lane  = threadIdx.x & 31;
    const int token = w >> 5;
    const int row   = w & 31;
    const int b     = token >> 10;
    const int s     = token & 1023;

    const float* src;
    float* dst;
    const float* gamma = nullptr;
    bool rope = true;
    if (row < 16) {
        src = qkv + (size_t)token * 2048 + row * 64;
        dst = q + ((size_t)(b * NH + row) * SS_ + s) * HD;
        gamma = qg;
    } else if (row < 24) {
        const int h = row - 16;
        src = qkv + (size_t)token * 2048 + 1024 + h * 64;
        dst = k + ((size_t)(b * NKH + h) * SS_ + s) * HD;
        gamma = kg;
    } else {
        const int h = row - 24;
        src = qkv + (size_t)token * 2048 + 1536 + h * 64;
        dst = v + ((size_t)(b * NKH + h) * SS_ + s) * HD;
        rope = false;
    }

    float x0 = src[lane];
    float x1 = src[lane + 32];
    float ssum = x0 * x0 + x1 * x1;
#pragma unroll
    for (int off = 16; off; off >>= 1)
        ssum += __shfl_xor_sync(0xffffffffu, ssum, off);
    const float r = rsqrtf(ssum * (1.0f / 64.0f) + 1e-6f);
    x0 *= r; x1 *= r;
    if (gamma) {
        x0 *= 1.0f + gamma[lane];
        x1 *= 1.0f + gamma[lane + 32];
    }
    if (rope) {
        const float px = (float)pos[token * 2 + 0];
        const float py = (float)pos[token * 2 + 1];
        const int j = lane & 15;
        // inv_freq = 10000^(-j/16) = exp2(-j/16 * log2(10000))
        const float invf = exp2f(-13.2877123795494f * (float)j * (1.0f / 16.0f));
        float s0, c0, s1, c1;
        sincosf(px * invf, &s0, &c0);
        sincosf(py * invf, &s1, &c1);
        const float p0 = __shfl_xor_sync(0xffffffffu, x0, 16);
        const float p1 = __shfl_xor_sync(0xffffffffu, x1, 16);
        if (lane < 16) { x0 = x0 * c0 - p0 * s0; x1 = x1 * c1 - p1 * s1; }
        else           { x0 = x0 * c0 + p0 * s0; x1 = x1 * c1 + p1 * s1; }
    }
    dst[lane]      = x0;
    dst[lane + 32] = x1;
}

// ---------------- flash attention (fp32, full mask, no scale) ----------------
// Block: one (b, h, 64-row q tile). 256 threads = 16x16, 4x4 register tiles.
__global__ __launch_bounds__(256)
void flash_attn(const float* __restrict__ gq, const float* __restrict__ gk,
                const float* __restrict__ gv, float* __restrict__ ao)
{
    extern __shared__ float sm[];
    float* Qt = sm;                 // [64][65] transposed: Qt[d*65 + r]
    float* Kt = Qt + 64 * 65;       // [64][65] transposed
    float* Ss = Kt + 64 * 65;       // [64][65] probs
    float* Vs = Ss + 64 * 65;       // [64][64] natural

    const int tid = threadIdx.x;
    const int tx  = tid & 15;
    const int ty  = tid >> 4;
    const int bh  = blockIdx.y;
    const int b   = bh >> 4;
    const int h   = bh & 15;
    const int kh  = h >> 1;               // GQA: groups = 2
    const int q0  = blockIdx.x * 64;

    const float* qb = gq + ((size_t)(b * NH  + h ) * SS_ + q0) * HD;
    const float* kb = gk + ((size_t)(b * NKH + kh) * SS_) * HD;
    const float* vb = gv + ((size_t)(b * NKH + kh) * SS_) * HD;

    for (int idx = tid; idx < 64 * 64; idx += 256) {
        const int rr = idx >> 6, dd = idx & 63;
        Qt[dd * 65 + rr] = qb[idx];
    }

    float m[4], l[4], o[4][4];
#pragma unroll
    for (int i = 0; i < 4; ++i) {
        m[i] = -1e30f; l[i] = 0.f;
#pragma unroll
        for (int j = 0; j < 4; ++j) o[i][j] = 0.f;
    }

    for (int kt = 0; kt < 16; ++kt) {
        __syncthreads();
        const float* kp = kb + (size_t)kt * 64 * HD;
        const float* vp = vb + (size_t)kt * 64 * HD;
        for (int idx = tid; idx < 64 * 64; idx += 256) {
            const int rr = idx >> 6, dd = idx & 63;
            Kt[dd * 65 + rr] = kp[idx];
            Vs[idx] = vp[idx];
        }
        __syncthreads();

        // S = Q K^T (64x64), each thread 4x4
        float s[4][4];
#pragma unroll
        for (int i = 0; i < 4; ++i)
#pragma unroll
            for (int j = 0; j < 4; ++j) s[i][j] = 0.f;

#pragma unroll 4
        for (int d = 0; d < 64; ++d) {
            float qr[4], kr[4];
#pragma unroll
            for (int i = 0; i < 4; ++i) qr[i] = Qt[d * 65 + ty * 4 + i];
#pragma unroll
            for (int j = 0; j < 4; ++j) kr[j] = Kt[d * 65 + tx * 4 + j];
#pragma unroll
            for (int i = 0; i < 4; ++i)
#pragma unroll
                for (int j = 0; j < 4; ++j)
                    s[i][j] = fmaf(qr[i], kr[j], s[i][j]);
        }

        // online softmax (row stats reduced over the 16 tx lanes in the half-warp)
#pragma unroll
        for (int i = 0; i < 4; ++i) {
            float mx = s[i][0];
#pragma unroll
            for (int j = 1; j < 4; ++j) mx = fmaxf(mx, s[i][j]);
#pragma unroll
            for (int off = 8; off; off >>= 1)
                mx = fmaxf(mx, __shfl_xor_sync(0xffffffffu, mx, off));
            const float mn = fmaxf(m[i], mx);
            const float alpha = __expf(m[i] - mn);
            m[i] = mn;
            float rs = 0.f;
#pragma unroll
            for (int j = 0; j < 4; ++j) {
                s[i][j] = __expf(s[i][j] - mn);
                rs += s[i][j];
            }
#pragma unroll
            for (int off = 8; off; off >>= 1)
                rs += __shfl_xor_sync(0xffffffffu, rs, off);
            l[i] = l[i] * alpha + rs;
#pragma unroll
            for (int j = 0; j < 4; ++j) {
                Ss[(ty * 4 + i) * 65 + tx * 4 + j] = s[i][j];
                o[i][j] *= alpha;
            }
        }
        __syncwarp();

        // O += P V  (P rows are produced/consumed within the same warp)
#pragma unroll 4
        for (int c = 0; c < 64; ++c) {
            const float4 vv = *(const float4*)&Vs[c * 64 + tx * 4];
            const float vr[4] = { vv.x, vv.y, vv.z, vv.w };
#pragma unroll
            for (int i = 0; i < 4; ++i) {
                const float p = Ss[(ty * 4 + i) * 65 + c];
#pragma unroll
                for (int j = 0; j < 4; ++j)
                    o[i][j] = fmaf(p, vr[j], o[i][j]);
            }
        }
        __syncwarp();
    }

#pragma unroll
    for (int i = 0; i < 4; ++i) {
        const int sq = q0 + ty * 4 + i;
        const float inv = 1.0f / l[i];
        float4 rv = make_float4(o[i][0] * inv, o[i][1] * inv, o[i][2] * inv, o[i][3] * inv);
        *(float4*)&ao[(((size_t)b * SS_ + sq) * NH + h) * HD + tx * 4] = rv;
    }
}

// ---------------- launch ----------------
extern "C" void kernel_launch(void* const* d_in, const int* in_sizes, int n_in,
                              void* d_out, int out_size)
{
    (void)in_sizes; (void)n_in; (void)out_size;
    const float* hidden = (const float*)d_in[0];
    const float* Wq     = (const float*)d_in[1];
    const float* Wk     = (const float*)d_in[2];
    const float* Wv     = (const float*)d_in[3];
    const float* Wo     = (const float*)d_in[4];
    const float* qg     = (const float*)d_in[5];
    const float* kg     = (const float*)d_in[6];
    const int*   pos    = (const int*)d_in[7];
    // d_in[8] = attention_mask: all-true in this problem, intentionally unused.
    float* out = (float*)d_out;

    float *qkv, *q, *k, *v, *ao;
    cudaGetSymbolAddress((void**)&qkv, g_qkv);
    cudaGetSymbolAddress((void**)&q,   g_q);
    cudaGetSymbolAddress((void**)&k,   g_k);
    cudaGetSymbolAddress((void**)&v,   g_v);
    cudaGetSymbolAddress((void**)&ao,  g_ao);

    const dim3 blk(256);

    // QKV projections into one scratch, ldc = 2048
    sgemm128<<<dim3(8, 32), blk>>>(hidden, Wq, qkv,          1024, HIDD, 1024, 2048);
    sgemm128<<<dim3(4, 32), blk>>>(hidden, Wk, qkv + 1024,   1024, HIDD,  512, 2048);
    sgemm128<<<dim3(4, 32), blk>>>(hidden, Wv, qkv + 1536,   1024, HIDD,  512, 2048);

    // RMSNorm + RoPE + transpose to [B,H,S,D]
    qkv_epilogue<<<TOKENS * 32 / 8, blk>>>(qkv, qg, kg, pos, q, k, v);

    // flash attention
    const size_t smem = (size_t)(3 * 64 * 65 + 64 * 64) * sizeof(float);  // 66304 B
    cudaFuncSetAttribute(flash_attn, cudaFuncAttributeMaxDynamicSharedMemorySize, (int)smem);
    flash_attn<<<dim3(SS_ / 64, BB * NH), blk, smem>>>(q, k, v, ao);

    // output projection
    sgemm128<<<dim3(8, 32), blk>>>(ao, Wo, out, 1024, 1024, 1024, 1024);
}

// round 2
// speedup vs baseline: 1.5412x; 1.5412x over previous
#include <cuda_runtime.h>
#include <cuda_bf16.h>
#include <math.h>

#define BB   4
#define SS_  1024
#define HIDD 1024
#define NH   16
#define NKH  8
#define HD   64
#define TOKENS (BB * SS_)   // 4096

// ---------------- scratch (no allocations allowed) ----------------
__device__ float g_qkv[(size_t)TOKENS * 2048];          // [token][0:1024 q | 1024:1536 k | 1536:2048 v]
__device__ float g_q[(size_t)BB * NH  * SS_ * HD];      // [b][h][s][d]
__device__ float g_k[(size_t)BB * NKH * SS_ * HD];
__device__ float g_v[(size_t)BB * NKH * SS_ * HD];
__device__ float g_ao[(size_t)TOKENS * NH * HD];        // [b*s][h*64+d]

// =====================================================================
// Tensor-core GEMM, fp32 accuracy via bf16 3-pass split.
// C[M,N] = A[M,K] @ B[K,N], row-major. M%128==0, N%128==0, K%32==0.
// BM=BN=128, BK=32, 256 threads, warp tile 32x64 (2x8 m16n8k16 tiles).
// =====================================================================
#define A_STRIDE 40    // 32 + 8 bf16 pad  (conflict-free ldmatrix)
#define B_STRIDE 136   // 128 + 8 bf16 pad

__device__ __forceinline__ void mma_bf16(float* d, const unsigned* a, const unsigned* b)
{
    asm volatile(
        "mma.sync.aligned.m16n8k16.row.col.f32.bf16.bf16.f32 "
        "{%0,%1,%2,%3}, {%4,%5,%6,%7}, {%8,%9}, {%0,%1,%2,%3};\n"
        : "+f"(d[0]), "+f"(d[1]), "+f"(d[2]), "+f"(d[3])
        : "r"(a[0]), "r"(a[1]), "r"(a[2]), "r"(a[3]), "r"(b[0]), "r"(b[1]));
}

__device__ __forceinline__ void ldsm_x4(unsigned* r, unsigned addr)
{
    asm volatile("ldmatrix.sync.aligned.m8n8.x4.shared.b16 {%0,%1,%2,%3}, [%4];\n"
                 : "=r"(r[0]), "=r"(r[1]), "=r"(r[2]), "=r"(r[3]) : "r"(addr));
}

__device__ __forceinline__ void ldsm_x2t(unsigned* r, unsigned addr)
{
    asm volatile("ldmatrix.sync.aligned.m8n8.x2.trans.shared.b16 {%0,%1}, [%2];\n"
                 : "=r"(r[0]), "=r"(r[1]) : "r"(addr));
}

__device__ __forceinline__ void split_store(__nv_bfloat16* hi, __nv_bfloat16* lo,
                                            float x, float y)
{
    __nv_bfloat162 h = __floats2bfloat162_rn(x, y);
    float hx = __bfloat162float(h.x);
    float hy = __bfloat162float(h.y);
    *(__nv_bfloat162*)hi = h;
    *(__nv_bfloat162*)lo = __floats2bfloat162_rn(x - hx, y - hy);
}

__global__ __launch_bounds__(256)
void gemm_bf16x3(const float* __restrict__ A, const float* __restrict__ Bm,
                 float* __restrict__ C, int K, int lda, int ldb, int ldc)
{
    __shared__ __nv_bfloat16 sAh[128 * A_STRIDE];
    __shared__ __nv_bfloat16 sAl[128 * A_STRIDE];
    __shared__ __nv_bfloat16 sBh[32 * B_STRIDE];
    __shared__ __nv_bfloat16 sBl[32 * B_STRIDE];

    const int tid  = threadIdx.x;
    const int lane = tid & 31;
    const int wid  = tid >> 5;
    const int wm   = wid >> 1;          // 0..3
    const int wn   = wid & 1;           // 0..1

    A  += (size_t)(blockIdx.y * 128) * lda;
    Bm += blockIdx.x * 128;
    C  += (size_t)(blockIdx.y * 128) * ldc + blockIdx.x * 128;

    // staging coords
    const int aRow = tid >> 3;          // 0..31 (stride 32 over 4 loads)
    const int aCol = (tid & 7) * 4;     // 0..28
    const int bRow = tid >> 5;          // 0..7  (stride 8 over 4 loads)
    const int bCol = (tid & 31) * 4;    // 0..124

    float acc[2][8][4];
#pragma unroll
    for (int i = 0; i < 2; ++i)
#pragma unroll
        for (int j = 0; j < 8; ++j)
#pragma unroll
            for (int t = 0; t < 4; ++t) acc[i][j][t] = 0.f;

    // smem byte base addresses for ldmatrix
    const unsigned sAh_b = (unsigned)__cvta_generic_to_shared(sAh);
    const unsigned sAl_b = (unsigned)__cvta_generic_to_shared(sAl);
    const unsigned sBh_b = (unsigned)__cvta_generic_to_shared(sBh);
    const unsigned sBl_b = (unsigned)__cvta_generic_to_shared(sBl);

    // A frag address: row = wm*32 + mt*16 + (lane&15), col = kc*16 + (lane>>4)*8
    const unsigned aAddrBase = ((wm * 32 + (lane & 15)) * A_STRIDE + (lane >> 4) * 8) * 2;
    // B frag address: row k = kc*16 + (lane&15), col = wn*64 + nt*8
    const unsigned bAddrBase = (((lane & 15)) * B_STRIDE + wn * 64) * 2;

    float4 ra[4], rb[4];
#pragma unroll
    for (int i = 0; i < 4; ++i) {
        ra[i] = *(const float4*)(A + (size_t)(aRow + i * 32) * lda + aCol);
        rb[i] = *(const float4*)(Bm + (size_t)(bRow + i * 8) * ldb + bCol);
    }

    const int iters = K >> 5;
    for (int it = 0; it < iters; ++it) {
        // ---- convert + store staged tile ----
#pragma unroll
        for (int i = 0; i < 4; ++i) {
            const int ar = aRow + i * 32;
            split_store(&sAh[ar * A_STRIDE + aCol],     &sAl[ar * A_STRIDE + aCol],     ra[i].x, ra[i].y);
            split_store(&sAh[ar * A_STRIDE + aCol + 2], &sAl[ar * A_STRIDE + aCol + 2], ra[i].z, ra[i].w);
            const int br = bRow + i * 8;
            split_store(&sBh[br * B_STRIDE + bCol],     &sBl[br * B_STRIDE + bCol],     rb[i].x, rb[i].y);
            split_store(&sBh[br * B_STRIDE + bCol + 2], &sBl[br * B_STRIDE + bCol + 2], rb[i].z, rb[i].w);
        }
        __syncthreads();

        // ---- prefetch next tile while mma runs ----
        if (it + 1 < iters) {
            const int k0 = (it + 1) * 32;
#pragma unroll
            for (int i = 0; i < 4; ++i) {
                ra[i] = *(const float4*)(A + (size_t)(aRow + i * 32) * lda + k0 + aCol);
                rb[i] = *(const float4*)(Bm + (size_t)(k0 + bRow + i * 8) * ldb + bCol);
            }
        }

        // ---- compute: 2 k-chunks of 16 ----
#pragma unroll
        for (int kc = 0; kc < 2; ++kc) {
            unsigned ah[2][4], al[2][4], bh[8][2], bl[8][2];
#pragma unroll
            for (int mt = 0; mt < 2; ++mt) {
                const unsigned off = aAddrBase + (mt * 16 * A_STRIDE + kc * 16) * 2;
                ldsm_x4(ah[mt], sAh_b + off);
                ldsm_x4(al[mt], sAl_b + off);
            }
#pragma unroll
            for (int nt = 0; nt < 8; ++nt) {
                const unsigned off = bAddrBase + (kc * 16 * B_STRIDE + nt * 8) * 2;
                ldsm_x2t(bh[nt], sBh_b + off);
                ldsm_x2t(bl[nt], sBl_b + off);
            }
#pragma unroll
            for (int mt = 0; mt < 2; ++mt)
#pragma unroll
                for (int nt = 0; nt < 8; ++nt) {
                    mma_bf16(acc[mt][nt], ah[mt], bh[nt]);
                    mma_bf16(acc[mt][nt], ah[mt], bl[nt]);
                    mma_bf16(acc[mt][nt], al[mt], bh[nt]);
                }
        }
        __syncthreads();
    }

    // ---- epilogue ----
    const int crow0 = wm * 32 + (lane >> 2);
    const int ccol0 = wn * 64 + (lane & 3) * 2;
#pragma unroll
    for (int mt = 0; mt < 2; ++mt)
#pragma unroll
        for (int nt = 0; nt < 8; ++nt) {
            float* p0 = C + (size_t)(crow0 + mt * 16) * ldc + ccol0 + nt * 8;
            float* p1 = p0 + 8 * ldc;
            *(float2*)p0 = make_float2(acc[mt][nt][0], acc[mt][nt][1]);
            *(float2*)p1 = make_float2(acc[mt][nt][2], acc[mt][nt][3]);
        }
}

// ---------------- RMSNorm + 2D RoPE epilogue ----------------
__global__ __launch_bounds__(256)
void qkv_epilogue(const float* __restrict__ qkv,
                  const float* __restrict__ qg, const float* __restrict__ kg,
                  const int* __restrict__ pos,
                  float* __restrict__ q, float* __restrict__ k, float* __restrict__ v)
{
    const int w     = (blockIdx.x * blockDim.x + threadIdx.x) >> 5;
    const int lane  = threadIdx.x & 31;
    const int token = w >> 5;
    const int row   = w & 31;
    const int b     = token >> 10;
    const int s     = token & 1023;

    const float* src;
    float* dst;
    const float* gamma = nullptr;
    bool rope = true;
    if (row < 16) {
        src = qkv + (size_t)token * 2048 + row * 64;
        dst = q + ((size_t)(b * NH + row) * SS_ + s) * HD;
        gamma = qg;
    } else if (row < 24) {
        const int h = row - 16;
        src = qkv + (size_t)token * 2048 + 1024 + h * 64;
        dst = k + ((size_t)(b * NKH + h) * SS_ + s) * HD;
        gamma = kg;
    } else {
        const int h = row - 24;
        src = qkv + (size_t)token * 2048 + 1536 + h * 64;
        dst = v + ((size_t)(b * NKH + h) * SS_ + s) * HD;
        rope = false;
    }

    float x0 = src[lane];
    float x1 = src[lane + 32];
    float ssum = x0 * x0 + x1 * x1;
#pragma unroll
    for (int off = 16; off; off >>= 1)
        ssum += __shfl_xor_sync(0xffffffffu, ssum, off);
    const float r = rsqrtf(ssum * (1.0f / 64.0f) + 1e-6f);
    x0 *= r; x1 *= r;
    if (gamma) {
        x0 *= 1.0f + gamma[lane];
        x1 *= 1.0f + gamma[lane + 32];
    }
    if (rope) {
        const float px = (float)pos[token * 2 + 0];
        const float py = (float)pos[token * 2 + 1];
        const int j = lane & 15;
        const float invf = exp2f(-13.2877123795494f * (float)j * (1.0f / 16.0f));
        float s0, c0, s1, c1;
        sincosf(px * invf, &s0, &c0);
        sincosf(py * invf, &s1, &c1);
        const float p0 = __shfl_xor_sync(0xffffffffu, x0, 16);
        const float p1 = __shfl_xor_sync(0xffffffffu, x1, 16);
        if (lane < 16) { x0 = x0 * c0 - p0 * s0; x1 = x1 * c1 - p1 * s1; }
        else           { x0 = x0 * c0 + p0 * s0; x1 = x1 * c1 + p1 * s1; }
    }
    dst[lane]      = x0;
    dst[lane + 32] = x1;
}

// ---------------- flash attention (fp32, full mask, no scale) ----------------
__global__ __launch_bounds__(256)
void flash_attn(const float* __restrict__ gq, const float* __restrict__ gk,
                const float* __restrict__ gv, float* __restrict__ ao)
{
    extern __shared__ float sm[];
    float* Qt = sm;                 // [64][65] transposed
    float* Kt = Qt + 64 * 65;       // [64][65] transposed
    float* Ss = Kt + 64 * 65;       // [64][65] probs
    float* Vs = Ss + 64 * 65;       // [64][64] natural

    const int tid = threadIdx.x;
    const int tx  = tid & 15;
    const int ty  = tid >> 4;
    const int bh  = blockIdx.y;
    const int b   = bh >> 4;
    const int h   = bh & 15;
    const int kh  = h >> 1;
    const int q0  = blockIdx.x * 64;

    const float* qb = gq + ((size_t)(b * NH  + h ) * SS_ + q0) * HD;
    const float* kb = gk + ((size_t)(b * NKH + kh) * SS_) * HD;
    const float* vb = gv + ((size_t)(b * NKH + kh) * SS_) * HD;

    for (int idx = tid; idx < 64 * 64; idx += 256) {
        const int rr = idx >> 6, dd = idx & 63;
        Qt[dd * 65 + rr] = qb[idx];
    }

    float m[4], l[4], o[4][4];
#pragma unroll
    for (int i = 0; i < 4; ++i) {
        m[i] = -1e30f; l[i] = 0.f;
#pragma unroll
        for (int j = 0; j < 4; ++j) o[i][j] = 0.f;
    }

    for (int kt = 0; kt < 16; ++kt) {
        __syncthreads();
        const float* kp = kb + (size_t)kt * 64 * HD;
        const float* vp = vb + (size_t)kt * 64 * HD;
        for (int idx = tid; idx < 64 * 64; idx += 256) {
            const int rr = idx >> 6, dd = idx & 63;
            Kt[dd * 65 + rr] = kp[idx];
            Vs[idx] = vp[idx];
        }
        __syncthreads();

        float s[4][4];
#pragma unroll
        for (int i = 0; i < 4; ++i)
#pragma unroll
            for (int j = 0; j < 4; ++j) s[i][j] = 0.f;

#pragma unroll 4
        for (int d = 0; d < 64; ++d) {
            float qr[4], kr[4];
#pragma unroll
            for (int i = 0; i < 4; ++i) qr[i] = Qt[d * 65 + ty * 4 + i];
#pragma unroll
            for (int j = 0; j < 4; ++j) kr[j] = Kt[d * 65 + tx * 4 + j];
#pragma unroll
            for (int i = 0; i < 4; ++i)
#pragma unroll
                for (int j = 0; j < 4; ++j)
                    s[i][j] = fmaf(qr[i], kr[j], s[i][j]);
        }

#pragma unroll
        for (int i = 0; i < 4; ++i) {
            float mx = s[i][0];
#pragma unroll
            for (int j = 1; j < 4; ++j) mx = fmaxf(mx, s[i][j]);
#pragma unroll
            for (int off = 8; off; off >>= 1)
                mx = fmaxf(mx, __shfl_xor_sync(0xffffffffu, mx, off));
            const float mn = fmaxf(m[i], mx);
            const float alpha = __expf(m[i] - mn);
            m[i] = mn;
            float rs = 0.f;
#pragma unroll
            for (int j = 0; j < 4; ++j) {
                s[i][j] = __expf(s[i][j] - mn);
                rs += s[i][j];
            }
#pragma unroll
            for (int off = 8; off; off >>= 1)
                rs += __shfl_xor_sync(0xffffffffu, rs, off);
            l[i] = l[i] * alpha + rs;
#pragma unroll
            for (int j = 0; j < 4; ++j) {
                Ss[(ty * 4 + i) * 65 + tx * 4 + j] = s[i][j];
                o[i][j] *= alpha;
            }
        }
        __syncwarp();

#pragma unroll 4
        for (int c = 0; c < 64; ++c) {
            const float4 vv = *(const float4*)&Vs[c * 64 + tx * 4];
            const float vr[4] = { vv.x, vv.y, vv.z, vv.w };
#pragma unroll
            for (int i = 0; i < 4; ++i) {
                const float p = Ss[(ty * 4 + i) * 65 + c];
#pragma unroll
                for (int j = 0; j < 4; ++j)
                    o[i][j] = fmaf(p, vr[j], o[i][j]);
            }
        }
        __syncwarp();
    }

#pragma unroll
    for (int i = 0; i < 4; ++i) {
        const int sq = q0 + ty * 4 + i;
        const float inv = 1.0f / l[i];
        float4 rv = make_float4(o[i][0] * inv, o[i][1] * inv, o[i][2] * inv, o[i][3] * inv);
        *(float4*)&ao[(((size_t)b * SS_ + sq) * NH + h) * HD + tx * 4] = rv;
    }
}

// ---------------- launch ----------------
extern "C" void kernel_launch(void* const* d_in, const int* in_sizes, int n_in,
                              void* d_out, int out_size)
{
    (void)in_sizes; (void)n_in; (void)out_size;
    const float* hidden = (const float*)d_in[0];
    const float* Wq     = (const float*)d_in[1];
    const float* Wk     = (const float*)d_in[2];
    const float* Wv     = (const float*)d_in[3];
    const float* Wo     = (const float*)d_in[4];
    const float* qg     = (const float*)d_in[5];
    const float* kg     = (const float*)d_in[6];
    const int*   pos    = (const int*)d_in[7];
    float* out = (float*)d_out;

    float *qkv, *q, *k, *v, *ao;
    cudaGetSymbolAddress((void**)&qkv, g_qkv);
    cudaGetSymbolAddress((void**)&q,   g_q);
    cudaGetSymbolAddress((void**)&k,   g_k);
    cudaGetSymbolAddress((void**)&v,   g_v);
    cudaGetSymbolAddress((void**)&ao,  g_ao);

    const dim3 blk(256);

    // QKV projections (tensor cores, bf16 3-pass split)
    gemm_bf16x3<<<dim3(8, 32), blk>>>(hidden, Wq, qkv,        1024, HIDD, 1024, 2048);
    gemm_bf16x3<<<dim3(4, 32), blk>>>(hidden, Wk, qkv + 1024, 1024, HIDD,  512, 2048);
    gemm_bf16x3<<<dim3(4, 32), blk>>>(hidden, Wv, qkv + 1536, 1024, HIDD,  512, 2048);

    // RMSNorm + RoPE + transpose to [B,H,S,D]
    qkv_epilogue<<<TOKENS * 32 / 8, blk>>>(qkv, qg, kg, pos, q, k, v);

    // flash attention (fp32 SIMT, unchanged this round)
    const size_t smem = (size_t)(3 * 64 * 65 + 64 * 64) * sizeof(float);
    cudaFuncSetAttribute(flash_attn, cudaFuncAttributeMaxDynamicSharedMemorySize, (int)smem);
    flash_attn<<<dim3(SS_ / 64, BB * NH), blk, smem>>>(q, k, v, ao);

    // output projection
    gemm_bf16x3<<<dim3(8, 32), blk>>>(ao, Wo, out, 1024, 1024, 1024, 1024);
}

// round 3
// speedup vs baseline: 2.0484x; 1.3291x over previous
#include <cuda_runtime.h>
#include <cuda_bf16.h>
#include <cuda_fp16.h>
#include <math.h>

#define BB   4
#define SS_  1024
#define HIDD 1024
#define NH   16
#define NKH  8
#define HD   64
#define TOKENS (BB * SS_)   // 4096

// ---------------- scratch (no allocations allowed) ----------------
__device__ float g_qkv[(size_t)TOKENS * 2048];
__device__ float g_q[(size_t)BB * NH  * SS_ * HD];      // [b][h][s][d]
__device__ float g_k[(size_t)BB * NKH * SS_ * HD];      // [b][kh][s][d]
__device__ float g_vt[(size_t)BB * NKH * HD * SS_];     // [b][kh][d][s]  (transposed V)
__device__ float g_ao[(size_t)TOKENS * NH * HD];        // [b*s][h*64+d]

// =====================================================================
// Tensor-core GEMM, fp32 accuracy via bf16 3-pass split (unchanged R2).
// =====================================================================
#define A_STRIDE 40
#define B_STRIDE 136

__device__ __forceinline__ void mma_bf16(float* d, const unsigned* a, const unsigned* b)
{
    asm volatile(
        "mma.sync.aligned.m16n8k16.row.col.f32.bf16.bf16.f32 "
        "{%0,%1,%2,%3}, {%4,%5,%6,%7}, {%8,%9}, {%0,%1,%2,%3};\n"
        : "+f"(d[0]), "+f"(d[1]), "+f"(d[2]), "+f"(d[3])
        : "r"(a[0]), "r"(a[1]), "r"(a[2]), "r"(a[3]), "r"(b[0]), "r"(b[1]));
}

__device__ __forceinline__ void mma_f16(float* d, const unsigned* a, const unsigned* b)
{
    asm volatile(
        "mma.sync.aligned.m16n8k16.row.col.f32.f16.f16.f32 "
        "{%0,%1,%2,%3}, {%4,%5,%6,%7}, {%8,%9}, {%0,%1,%2,%3};\n"
        : "+f"(d[0]), "+f"(d[1]), "+f"(d[2]), "+f"(d[3])
        : "r"(a[0]), "r"(a[1]), "r"(a[2]), "r"(a[3]), "r"(b[0]), "r"(b[1]));
}

__device__ __forceinline__ void ldsm_x4(unsigned* r, unsigned addr)
{
    asm volatile("ldmatrix.sync.aligned.m8n8.x4.shared.b16 {%0,%1,%2,%3}, [%4];\n"
                 : "=r"(r[0]), "=r"(r[1]), "=r"(r[2]), "=r"(r[3]) : "r"(addr));
}

__device__ __forceinline__ void ldsm_x2t(unsigned* r, unsigned addr)
{
    asm volatile("ldmatrix.sync.aligned.m8n8.x2.trans.shared.b16 {%0,%1}, [%2];\n"
                 : "=r"(r[0]), "=r"(r[1]) : "r"(addr));
}

__device__ __forceinline__ void split_store(__nv_bfloat16* hi, __nv_bfloat16* lo,
                                            float x, float y)
{
    __nv_bfloat162 h = __floats2bfloat162_rn(x, y);
    float hx = __bfloat162float(h.x);
    float hy = __bfloat162float(h.y);
    *(__nv_bfloat162*)hi = h;
    *(__nv_bfloat162*)lo = __floats2bfloat162_rn(x - hx, y - hy);
}

__global__ __launch_bounds__(256)
void gemm_bf16x3(const float* __restrict__ A, const float* __restrict__ Bm,
                 float* __restrict__ C, int K, int lda, int ldb, int ldc)
{
    __shared__ __nv_bfloat16 sAh[128 * A_STRIDE];
    __shared__ __nv_bfloat16 sAl[128 * A_STRIDE];
    __shared__ __nv_bfloat16 sBh[32 * B_STRIDE];
    __shared__ __nv_bfloat16 sBl[32 * B_STRIDE];

    const int tid  = threadIdx.x;
    const int lane = tid & 31;
    const int wid  = tid >> 5;
    const int wm   = wid >> 1;
    const int wn   = wid & 1;

    A  += (size_t)(blockIdx.y * 128) * lda;
    Bm += blockIdx.x * 128;
    C  += (size_t)(blockIdx.y * 128) * ldc + blockIdx.x * 128;

    const int aRow = tid >> 3;
    const int aCol = (tid & 7) * 4;
    const int bRow = tid >> 5;
    const int bCol = (tid & 31) * 4;

    float acc[2][8][4];
#pragma unroll
    for (int i = 0; i < 2; ++i)
#pragma unroll
        for (int j = 0; j < 8; ++j)
#pragma unroll
            for (int t = 0; t < 4; ++t) acc[i][j][t] = 0.f;

    const unsigned sAh_b = (unsigned)__cvta_generic_to_shared(sAh);
    const unsigned sAl_b = (unsigned)__cvta_generic_to_shared(sAl);
    const unsigned sBh_b = (unsigned)__cvta_generic_to_shared(sBh);
    const unsigned sBl_b = (unsigned)__cvta_generic_to_shared(sBl);

    const unsigned aAddrBase = ((wm * 32 + (lane & 15)) * A_STRIDE + (lane >> 4) * 8) * 2;
    const unsigned bAddrBase = (((lane & 15)) * B_STRIDE + wn * 64) * 2;

    float4 ra[4], rb[4];
#pragma unroll
    for (int i = 0; i < 4; ++i) {
        ra[i] = *(const float4*)(A + (size_t)(aRow + i * 32) * lda + aCol);
        rb[i] = *(const float4*)(Bm + (size_t)(bRow + i * 8) * ldb + bCol);
    }

    const int iters = K >> 5;
    for (int it = 0; it < iters; ++it) {
#pragma unroll
        for (int i = 0; i < 4; ++i) {
            const int ar = aRow + i * 32;
            split_store(&sAh[ar * A_STRIDE + aCol],     &sAl[ar * A_STRIDE + aCol],     ra[i].x, ra[i].y);
            split_store(&sAh[ar * A_STRIDE + aCol + 2], &sAl[ar * A_STRIDE + aCol + 2], ra[i].z, ra[i].w);
            const int br = bRow + i * 8;
            split_store(&sBh[br * B_STRIDE + bCol],     &sBl[br * B_STRIDE + bCol],     rb[i].x, rb[i].y);
            split_store(&sBh[br * B_STRIDE + bCol + 2], &sBl[br * B_STRIDE + bCol + 2], rb[i].z, rb[i].w);
        }
        __syncthreads();

        if (it + 1 < iters) {
            const int k0 = (it + 1) * 32;
#pragma unroll
            for (int i = 0; i < 4; ++i) {
                ra[i] = *(const float4*)(A + (size_t)(aRow + i * 32) * lda + k0 + aCol);
                rb[i] = *(const float4*)(Bm + (size_t)(k0 + bRow + i * 8) * ldb + bCol);
            }
        }

#pragma unroll
        for (int kc = 0; kc < 2; ++kc) {
            unsigned ah[2][4], al[2][4], bh[8][2], bl[8][2];
#pragma unroll
            for (int mt = 0; mt < 2; ++mt) {
                const unsigned off = aAddrBase + (mt * 16 * A_STRIDE + kc * 16) * 2;
                ldsm_x4(ah[mt], sAh_b + off);
                ldsm_x4(al[mt], sAl_b + off);
            }
#pragma unroll
            for (int nt = 0; nt < 8; ++nt) {
                const unsigned off = bAddrBase + (kc * 16 * B_STRIDE + nt * 8) * 2;
                ldsm_x2t(bh[nt], sBh_b + off);
                ldsm_x2t(bl[nt], sBl_b + off);
            }
#pragma unroll
            for (int mt = 0; mt < 2; ++mt)
#pragma unroll
                for (int nt = 0; nt < 8; ++nt) {
                    mma_bf16(acc[mt][nt], ah[mt], bh[nt]);
                    mma_bf16(acc[mt][nt], ah[mt], bl[nt]);
                    mma_bf16(acc[mt][nt], al[mt], bh[nt]);
                }
        }
        __syncthreads();
    }

    const int crow0 = wm * 32 + (lane >> 2);
    const int ccol0 = wn * 64 + (lane & 3) * 2;
#pragma unroll
    for (int mt = 0; mt < 2; ++mt)
#pragma unroll
        for (int nt = 0; nt < 8; ++nt) {
            float* p0 = C + (size_t)(crow0 + mt * 16) * ldc + ccol0 + nt * 8;
            float* p1 = p0 + 8 * ldc;
            *(float2*)p0 = make_float2(acc[mt][nt][0], acc[mt][nt][1]);
            *(float2*)p1 = make_float2(acc[mt][nt][2], acc[mt][nt][3]);
        }
}

// ---------------- RMSNorm + 2D RoPE epilogue (V written transposed) ----------------
__global__ __launch_bounds__(256)
void qkv_epilogue(const float* __restrict__ qkv,
                  const float* __restrict__ qg, const float* __restrict__ kg,
                  const int* __restrict__ pos,
                  float* __restrict__ q, float* __restrict__ k, float* __restrict__ vt)
{
    const int w     = (blockIdx.x * blockDim.x + threadIdx.x) >> 5;
    const int lane  = threadIdx.x & 31;
    const int token = w >> 5;
    const int row   = w & 31;
    const int b     = token >> 10;
    const int s     = token & 1023;

    const float* src;
    float* dst = nullptr;
    float* vdst = nullptr;
    const float* gamma = nullptr;
    bool rope = true;
    if (row < 16) {
        src = qkv + (size_t)token * 2048 + row * 64;
        dst = q + ((size_t)(b * NH + row) * SS_ + s) * HD;
        gamma = qg;
    } else if (row < 24) {
        const int h = row - 16;
        src = qkv + (size_t)token * 2048 + 1024 + h * 64;
        dst = k + ((size_t)(b * NKH + h) * SS_ + s) * HD;
        gamma = kg;
    } else {
        const int h = row - 24;
        src = qkv + (size_t)token * 2048 + 1536 + h * 64;
        vdst = vt + ((size_t)(b * NKH + h) * HD) * SS_ + s;   // column s of [d][s]
        rope = false;
    }

    float x0 = src[lane];
    float x1 = src[lane + 32];
    float ssum = x0 * x0 + x1 * x1;
#pragma unroll
    for (int off = 16; off; off >>= 1)
        ssum += __shfl_xor_sync(0xffffffffu, ssum, off);
    const float r = rsqrtf(ssum * (1.0f / 64.0f) + 1e-6f);
    x0 *= r; x1 *= r;
    if (gamma) {
        x0 *= 1.0f + gamma[lane];
        x1 *= 1.0f + gamma[lane + 32];
    }
    if (rope) {
        const float px = (float)pos[token * 2 + 0];
        const float py = (float)pos[token * 2 + 1];
        const int j = lane & 15;
        const float invf = exp2f(-13.2877123795494f * (float)j * (1.0f / 16.0f));
        float s0, c0, s1, c1;
        sincosf(px * invf, &s0, &c0);
        sincosf(py * invf, &s1, &c1);
        const float p0 = __shfl_xor_sync(0xffffffffu, x0, 16);
        const float p1 = __shfl_xor_sync(0xffffffffu, x1, 16);
        if (lane < 16) { x0 = x0 * c0 - p0 * s0; x1 = x1 * c1 - p1 * s1; }
        else           { x0 = x0 * c0 + p0 * s0; x1 = x1 * c1 + p1 * s1; }
        dst[lane]      = x0;
        dst[lane + 32] = x1;
    } else if (vdst) {
        vdst[(size_t)lane * SS_]        = x0;
        vdst[(size_t)(lane + 32) * SS_] = x1;
    } else {
        dst[lane]      = x0;
        dst[lane + 32] = x1;
    }
}

// =====================================================================
// Flash attention on tensor cores.
// Block = 128 q-rows of one (b,h); 8 warps, each owns 16 rows x full d.
// No smem, no __syncthreads: fragments loaded directly from gmem (L1-shared).
// QK^T: bf16 3-pass split. PV: fp16 P (single) x fp16 V (hi/lo split, 2-pass).
// =====================================================================
__device__ __forceinline__ void fsplit_bf16(float x, float y, unsigned& hi, unsigned& lo)
{
    __nv_bfloat162 h = __floats2bfloat162_rn(x, y);
    hi = *(unsigned*)&h;
    __nv_bfloat162 l = __floats2bfloat162_rn(x - __bfloat162float(h.x),
                                             y - __bfloat162float(h.y));
    lo = *(unsigned*)&l;
}

__device__ __forceinline__ void fsplit_f16(float x, float y, unsigned& hi, unsigned& lo)
{
    __half2 h = __floats2half2_rn(x, y);
    hi = *(unsigned*)&h;
    __half2 l = __floats2half2_rn(x - __half2float(__low2half(h)),
                                  y - __half2float(__high2half(h)));
    lo = *(unsigned*)&l;
}

__global__ __launch_bounds__(256, 1)
void flash_attn_mma(const float* __restrict__ gq, const float* __restrict__ gk,
                    const float* __restrict__ gvt, float* __restrict__ ao)
{
    const int lane = threadIdx.x & 31;
    const int w    = threadIdx.x >> 5;
    const int bh   = blockIdx.y;
    const int b    = bh >> 4;
    const int h    = bh & 15;
    const int kh   = h >> 1;
    const int q0   = blockIdx.x * 128 + w * 16;   // this warp's first q row

    const int r  = lane >> 2;        // 0..7
    const int cq = (lane & 3) * 2;   // 0,2,4,6

    const float* qb = gq  + ((size_t)(b * NH  + h ) * SS_ + q0) * HD;
    const float* kb = gk  + ((size_t)(b * NKH + kh) * SS_) * HD;
    const float* vt = gvt + ((size_t)(b * NKH + kh) * HD) * SS_;

    // ---- Q fragments (held for the whole kernel) ----
    unsigned qh[4][4], ql[4][4];
#pragma unroll
    for (int kc = 0; kc < 4; ++kc)
#pragma unroll
        for (int i = 0; i < 4; ++i) {
            const int row = r + (i & 1) * 8;
            const int col = kc * 16 + cq + (i & 2) * 4;
            float2 t = *(const float2*)(qb + (size_t)row * HD + col);
            fsplit_bf16(t.x, t.y, qh[kc][i], ql[kc][i]);
        }

    float o[8][4];
#pragma unroll
    for (int nt = 0; nt < 8; ++nt)
#pragma unroll
        for (int j = 0; j < 4; ++j) o[nt][j] = 0.f;
    float m0 = -1e30f, m1 = -1e30f, l0 = 0.f, l1 = 0.f;

    for (int kt = 0; kt < 16; ++kt) {
        const float* kp = kb + (size_t)kt * 64 * HD;

        float s[8][4];
#pragma unroll
        for (int nt = 0; nt < 8; ++nt)
#pragma unroll
            for (int j = 0; j < 4; ++j) s[nt][j] = 0.f;

        // ---- S = Q K^T (bf16 3-pass) ----
#pragma unroll
        for (int kc = 0; kc < 4; ++kc) {
            unsigned kfh[8][2], kfl[8][2];
#pragma unroll
            for (int nt = 0; nt < 8; ++nt) {
                const float* rowp = kp + (size_t)(nt * 8 + r) * HD + kc * 16 + cq;
                float2 t0 = *(const float2*)rowp;
                float2 t1 = *(const float2*)(rowp + 8);
                fsplit_bf16(t0.x, t0.y, kfh[nt][0], kfl[nt][0]);
                fsplit_bf16(t1.x, t1.y, kfh[nt][1], kfl[nt][1]);
            }
#pragma unroll
            for (int nt = 0; nt < 8; ++nt) {
                mma_bf16(s[nt], qh[kc], kfh[nt]);
                mma_bf16(s[nt], qh[kc], kfl[nt]);
                mma_bf16(s[nt], ql[kc], kfh[nt]);
            }
        }

        // ---- online softmax (rows r and r+8, quad-local reduce) ----
        float mx0 = s[0][0], mx1 = s[0][2];
#pragma unroll
        for (int nt = 0; nt < 8; ++nt) {
            mx0 = fmaxf(mx0, fmaxf(s[nt][0], s[nt][1]));
            mx1 = fmaxf(mx1, fmaxf(s[nt][2], s[nt][3]));
        }
        mx0 = fmaxf(mx0, __shfl_xor_sync(0xffffffffu, mx0, 1));
        mx0 = fmaxf(mx0, __shfl_xor_sync(0xffffffffu, mx0, 2));
        mx1 = fmaxf(mx1, __shfl_xor_sync(0xffffffffu, mx1, 1));
        mx1 = fmaxf(mx1, __shfl_xor_sync(0xffffffffu, mx1, 2));

        const float mn0 = fmaxf(m0, mx0);
        const float mn1 = fmaxf(m1, mx1);
        const float al0 = __expf(m0 - mn0);
        const float al1 = __expf(m1 - mn1);
        m0 = mn0; m1 = mn1;

        float rs0 = 0.f, rs1 = 0.f;
#pragma unroll
        for (int nt = 0; nt < 8; ++nt) {
            s[nt][0] = __expf(s[nt][0] - mn0);
            s[nt][1] = __expf(s[nt][1] - mn0);
            s[nt][2] = __expf(s[nt][2] - mn1);
            s[nt][3] = __expf(s[nt][3] - mn1);
            rs0 += s[nt][0] + s[nt][1];
            rs1 += s[nt][2] + s[nt][3];
        }
        rs0 += __shfl_xor_sync(0xffffffffu, rs0, 1);
        rs0 += __shfl_xor_sync(0xffffffffu, rs0, 2);
        rs1 += __shfl_xor_sync(0xffffffffu, rs1, 1);
        rs1 += __shfl_xor_sync(0xffffffffu, rs1, 2);
        l0 = l0 * al0 + rs0;
        l1 = l1 * al1 + rs1;

#pragma unroll
        for (int nt = 0; nt < 8; ++nt) {
            o[nt][0] *= al0; o[nt][1] *= al0;
            o[nt][2] *= al1; o[nt][3] *= al1;
        }

        // ---- O += P V (fp16, V split 2-pass) ----
#pragma unroll
        for (int kc = 0; kc < 4; ++kc) {
            unsigned pa[4];
            {
                __half2 t;
                t = __floats2half2_rn(s[2 * kc][0],     s[2 * kc][1]);     pa[0] = *(unsigned*)&t;
                t = __floats2half2_rn(s[2 * kc][2],     s[2 * kc][3]);     pa[1] = *(unsigned*)&t;
                t = __floats2half2_rn(s[2 * kc + 1][0], s[2 * kc + 1][1]); pa[2] = *(unsigned*)&t;
                t = __floats2half2_rn(s[2 * kc + 1][2], s[2 * kc + 1][3]); pa[3] = *(unsigned*)&t;
            }
#pragma unroll
            for (int ntd = 0; ntd < 8; ++ntd) {
                const float* vp = vt + (size_t)(ntd * 8 + r) * SS_ + kt * 64 + kc * 16 + cq;
                float2 v0 = *(const float2*)vp;
                float2 v1 = *(const float2*)(vp + 8);
                unsigned vh[2], vl[2];
                fsplit_f16(v0.x, v0.y, vh[0], vl[0]);
                fsplit_f16(v1.x, v1.y, vh[1], vl[1]);
                mma_f16(o[ntd], pa, vh);
                mma_f16(o[ntd], pa, vl);
            }
        }
    }

    // ---- write O / l ----
    const float inv0 = 1.0f / l0;
    const float inv1 = 1.0f / l1;
    const int sg0 = q0 + r;
    const int sg1 = q0 + r + 8;
    float* a0 = ao + (((size_t)b * SS_ + sg0) * NH + h) * HD;
    float* a1 = ao + (((size_t)b * SS_ + sg1) * NH + h) * HD;
#pragma unroll
    for (int ntd = 0; ntd < 8; ++ntd) {
        *(float2*)(a0 + ntd * 8 + cq) = make_float2(o[ntd][0] * inv0, o[ntd][1] * inv0);
        *(float2*)(a1 + ntd * 8 + cq) = make_float2(o[ntd][2] * inv1, o[ntd][3] * inv1);
    }
}

// ---------------- launch ----------------
extern "C" void kernel_launch(void* const* d_in, const int* in_sizes, int n_in,
                              void* d_out, int out_size)
{
    (void)in_sizes; (void)n_in; (void)out_size;
    const float* hidden = (const float*)d_in[0];
    const float* Wq     = (const float*)d_in[1];
    const float* Wk     = (const float*)d_in[2];
    const float* Wv     = (const float*)d_in[3];
    const float* Wo     = (const float*)d_in[4];
    const float* qg     = (const float*)d_in[5];
    const float* kg     = (const float*)d_in[6];
    const int*   pos    = (const int*)d_in[7];
    float* out = (float*)d_out;

    float *qkv, *q, *k, *vt, *ao;
    cudaGetSymbolAddress((void**)&qkv, g_qkv);
    cudaGetSymbolAddress((void**)&q,   g_q);
    cudaGetSymbolAddress((void**)&k,   g_k);
    cudaGetSymbolAddress((void**)&vt,  g_vt);
    cudaGetSymbolAddress((void**)&ao,  g_ao);

    const dim3 blk(256);

    gemm_bf16x3<<<dim3(8, 32), blk>>>(hidden, Wq, qkv,        1024, HIDD, 1024, 2048);
    gemm_bf16x3<<<dim3(4, 32), blk>>>(hidden, Wk, qkv + 1024, 1024, HIDD,  512, 2048);
    gemm_bf16x3<<<dim3(4, 32), blk>>>(hidden, Wv, qkv + 1536, 1024, HIDD,  512, 2048);

    qkv_epilogue<<<TOKENS * 32 / 8, blk>>>(qkv, qg, kg, pos, q, k, vt);

    flash_attn_mma<<<dim3(SS_ / 128, BB * NH), blk>>>(q, k, vt, ao);

    gemm_bf16x3<<<dim3(8, 32), blk>>>(ao, Wo, out, 1024, 1024, 1024, 1024);
}

// round 5
// speedup vs baseline: 2.0759x; 1.0134x over previous
#include <cuda_runtime.h>
#include <cuda_bf16.h>
#include <cuda_fp16.h>
#include <math.h>
#include <stdint.h>

#define BB   4
#define SS_  1024
#define HIDD 1024
#define NH   16
#define NKH  8
#define HD   64
#define TOKENS (BB * SS_)   // 4096

// ---------------- scratch (no allocations allowed) ----------------
__device__ float g_qkv[(size_t)TOKENS * 2048];
__device__ float g_q[(size_t)BB * NH  * SS_ * HD];
__device__ float g_k[(size_t)BB * NKH * SS_ * HD];
__device__ float g_vt[(size_t)BB * NKH * HD * SS_];
__device__ float g_ao[(size_t)TOKENS * NH * HD];

__device__ __align__(256) __nv_bfloat16 g_ah [(size_t)TOKENS * 1024];   // hidden hi
__device__ __align__(256) __nv_bfloat16 g_al [(size_t)TOKENS * 1024];   // hidden lo
__device__ __align__(256) __nv_bfloat16 g_wth[(size_t)2048 * 1024];     // [Wq;Wk;Wv]^T hi  [n][k]
__device__ __align__(256) __nv_bfloat16 g_wtl[(size_t)2048 * 1024];
__device__ __align__(256) __nv_bfloat16 g_oth[(size_t)1024 * 1024];     // Wo^T hi [n][k]
__device__ __align__(256) __nv_bfloat16 g_otl[(size_t)1024 * 1024];
__device__ __align__(256) __nv_bfloat16 g_aoh[(size_t)TOKENS * 1024];
__device__ __align__(256) __nv_bfloat16 g_aol[(size_t)TOKENS * 1024];

// ================= mma / ldmatrix helpers =================
__device__ __forceinline__ void mma_bf16(float* d, const unsigned* a, const unsigned* b)
{
    asm volatile(
        "mma.sync.aligned.m16n8k16.row.col.f32.bf16.bf16.f32 "
        "{%0,%1,%2,%3}, {%4,%5,%6,%7}, {%8,%9}, {%0,%1,%2,%3};\n"
        : "+f"(d[0]), "+f"(d[1]), "+f"(d[2]), "+f"(d[3])
        : "r"(a[0]), "r"(a[1]), "r"(a[2]), "r"(a[3]), "r"(b[0]), "r"(b[1]));
}
__device__ __forceinline__ void mma_f16r(float* d, const unsigned* a, const unsigned* b)
{
    asm volatile(
        "mma.sync.aligned.m16n8k16.row.col.f32.f16.f16.f32 "
        "{%0,%1,%2,%3}, {%4,%5,%6,%7}, {%8,%9}, {%0,%1,%2,%3};\n"
        : "+f"(d[0]), "+f"(d[1]), "+f"(d[2]), "+f"(d[3])
        : "r"(a[0]), "r"(a[1]), "r"(a[2]), "r"(a[3]), "r"(b[0]), "r"(b[1]));
}
__device__ __forceinline__ void ldsm_x4(unsigned* r, unsigned addr)
{
    asm volatile("ldmatrix.sync.aligned.m8n8.x4.shared.b16 {%0,%1,%2,%3}, [%4];\n"
                 : "=r"(r[0]), "=r"(r[1]), "=r"(r[2]), "=r"(r[3]) : "r"(addr));
}

// ================= converts (one-time pre-split) =================
__global__ __launch_bounds__(256)
void convert_split(const float* __restrict__ X, __nv_bfloat16* __restrict__ H,
                   __nv_bfloat16* __restrict__ L, int n4)
{
    const int i = blockIdx.x * 256 + threadIdx.x;
    if (i >= n4) return;
    float4 v = ((const float4*)X)[i];
    __nv_bfloat162 h0 = __floats2bfloat162_rn(v.x, v.y);
    __nv_bfloat162 h1 = __floats2bfloat162_rn(v.z, v.w);
    __nv_bfloat162 l0 = __floats2bfloat162_rn(v.x - __bfloat162float(h0.x), v.y - __bfloat162float(h0.y));
    __nv_bfloat162 l1 = __floats2bfloat162_rn(v.z - __bfloat162float(h1.x), v.w - __bfloat162float(h1.y));
    *(__nv_bfloat162*)&H[(size_t)4 * i]     = h0;
    *(__nv_bfloat162*)&H[(size_t)4 * i + 2] = h1;
    *(__nv_bfloat162*)&L[(size_t)4 * i]     = l0;
    *(__nv_bfloat162*)&L[(size_t)4 * i + 2] = l1;
}

// W [1024 k][N n] fp32 -> TH/TL [n][1024 k] bf16
__global__ __launch_bounds__(256)
void transpose_split(const float* __restrict__ W, __nv_bfloat16* __restrict__ TH,
                     __nv_bfloat16* __restrict__ TL, int N)
{
    __shared__ float t[32][33];
    const int tx = threadIdx.x & 31;
    const int ty = threadIdx.x >> 5;
    const int n0 = blockIdx.x * 32, k0 = blockIdx.y * 32;
#pragma unroll
    for (int j = 0; j < 4; ++j)
        t[ty + 8 * j][tx] = W[(size_t)(k0 + ty + 8 * j) * N + n0 + tx];
    __syncthreads();
#pragma unroll
    for (int j = 0; j < 4; ++j) {
        const int n = ty + 8 * j;
        const float v = t[tx][n];
        const __nv_bfloat16 h = __float2bfloat16(v);
        TH[(size_t)(n0 + n) * 1024 + k0 + tx] = h;
        TL[(size_t)(n0 + n) * 1024 + k0 + tx] = __float2bfloat16(v - __bfloat162float(h));
    }
}

// ================= legacy-mma GEMM on pre-split operands =================
// C[M,N] fp32 = Ah/Al [M][1024] @ (Bh/Bl [N][1024])^T, bf16 3-pass.
// Tile 128x128, BK=32, 256 thr, warp tile 32x64, cp.async double buffer.
#define PK 40                                  // padded K stride (bf16 elems)
#define MAT_ELEMS (128 * PK)                   // one matrix buffer
#define STAGE_ELEMS (4 * MAT_ELEMS)            // Ah,Al,Bh,Bl
#define GEMM_SMEM (2 * STAGE_ELEMS * 2)        // bytes: 81920

__global__ __launch_bounds__(256, 1)
void gemm_presplit(const __nv_bfloat16* __restrict__ Ah, const __nv_bfloat16* __restrict__ Al,
                   const __nv_bfloat16* __restrict__ Bh, const __nv_bfloat16* __restrict__ Bl,
                   float* __restrict__ C, int ldc)
{
    extern __shared__ __nv_bfloat16 sm[];

    const int tid  = threadIdx.x;
    const int lane = tid & 31;
    const int wid  = tid >> 5;
    const int wm   = wid & 3;            // 4 m-warps
    const int wn   = wid >> 2;           // 2 n-warps
    const int m0   = blockIdx.y * 128;
    const int n0   = blockIdx.x * 128;

    const __nv_bfloat16* srcs[4] = {
        Ah + (size_t)m0 * 1024, Al + (size_t)m0 * 1024,
        Bh + (size_t)n0 * 1024, Bl + (size_t)n0 * 1024 };

    const unsigned smb = (unsigned)__cvta_generic_to_shared(sm);

    // stage K-block kb (cols kb*32..+31 of all four matrices) into buffer buf
    auto stage = [&](int kb, int buf) {
        const unsigned dbase = smb + (unsigned)buf * STAGE_ELEMS * 2;
#pragma unroll
        for (int mat = 0; mat < 4; ++mat) {
            const __nv_bfloat16* s = srcs[mat];
            const unsigned mb = dbase + (unsigned)mat * MAT_ELEMS * 2;
#pragma unroll
            for (int j = 0; j < 2; ++j) {
                const int chunk = tid + j * 256;      // 0..511
                const int row   = chunk >> 2;         // 0..127
                const int c8    = (chunk & 3) * 8;    // 0,8,16,24
                const __nv_bfloat16* sp = s + (size_t)row * 1024 + kb * 32 + c8;
                const unsigned dst = mb + (unsigned)(row * PK + c8) * 2;
                asm volatile("cp.async.cg.shared.global [%0], [%1], 16;\n" :: "r"(dst), "l"(sp));
            }
        }
        asm volatile("cp.async.commit_group;\n" ::: "memory");
    };

    float acc[2][8][4];
#pragma unroll
    for (int i = 0; i < 2; ++i)
#pragma unroll
        for (int j = 0; j < 8; ++j)
#pragma unroll
            for (int t = 0; t < 4; ++t) acc[i][j][t] = 0.f;

    // ldmatrix address bases (lane layout: (lane&15) rows, (lane>>4)*8 k-offset)
    const unsigned aOff = (unsigned)((wm * 32 + (lane & 15)) * PK + (lane >> 4) * 8) * 2;
    const unsigned bOff = (unsigned)((wn * 64 + (lane & 15)) * PK + (lane >> 4) * 8) * 2;

    stage(0, 0);

    const int KB = 1024 / 32;
    for (int kb = 0; kb < KB; ++kb) {
        const int cur = kb & 1;
        if (kb + 1 < KB) {
            stage(kb + 1, cur ^ 1);
            asm volatile("cp.async.wait_group 1;\n" ::: "memory");
        } else {
            asm volatile("cp.async.wait_group 0;\n" ::: "memory");
        }
        __syncthreads();

        const unsigned base = smb + (unsigned)cur * STAGE_ELEMS * 2;
        const unsigned bAh = base;
        const unsigned bAl = base + MAT_ELEMS * 2;
        const unsigned bBh = base + 2 * MAT_ELEMS * 2;
        const unsigned bBl = base + 3 * MAT_ELEMS * 2;

#pragma unroll
        for (int kc = 0; kc < 2; ++kc) {
            const unsigned ko = (unsigned)(kc * 16) * 2;
            unsigned ah[2][4], al[2][4], bh[4][4], bl[4][4];
#pragma unroll
            for (int mt = 0; mt < 2; ++mt) {
                const unsigned o = aOff + (unsigned)(mt * 16 * PK) * 2 + ko;
                ldsm_x4(ah[mt], bAh + o);
                ldsm_x4(al[mt], bAl + o);
            }
#pragma unroll
            for (int nb = 0; nb < 4; ++nb) {
                const unsigned o = bOff + (unsigned)(nb * 16 * PK) * 2 + ko;
                ldsm_x4(bh[nb], bBh + o);
                ldsm_x4(bl[nb], bBl + o);
            }
#pragma unroll
            for (int mt = 0; mt < 2; ++mt)
#pragma unroll
                for (int nb = 0; nb < 4; ++nb) {
                    unsigned b0h[2] = { bh[nb][0], bh[nb][2] };   // rows nb*16+0..7
                    unsigned b1h[2] = { bh[nb][1], bh[nb][3] };   // rows nb*16+8..15
                    unsigned b0l[2] = { bl[nb][0], bl[nb][2] };
                    unsigned b1l[2] = { bl[nb][1], bl[nb][3] };
                    mma_bf16(acc[mt][2 * nb],     ah[mt], b0h);
                    mma_bf16(acc[mt][2 * nb],     ah[mt], b0l);
                    mma_bf16(acc[mt][2 * nb],     al[mt], b0h);
                    mma_bf16(acc[mt][2 * nb + 1], ah[mt], b1h);
                    mma_bf16(acc[mt][2 * nb + 1], ah[mt], b1l);
                    mma_bf16(acc[mt][2 * nb + 1], al[mt], b1h);
                }
        }
        __syncthreads();
    }

    // epilogue
    const int crow0 = m0 + wm * 32 + (lane >> 2);
    const int ccol0 = n0 + wn * 64 + (lane & 3) * 2;
#pragma unroll
    for (int mt = 0; mt < 2; ++mt)
#pragma unroll
        for (int nt = 0; nt < 8; ++nt) {
            float* p0 = C + (size_t)(crow0 + mt * 16) * ldc + ccol0 + nt * 8;
            float* p1 = p0 + 8 * ldc;
            *(float2*)p0 = make_float2(acc[mt][nt][0], acc[mt][nt][1]);
            *(float2*)p1 = make_float2(acc[mt][nt][2], acc[mt][nt][3]);
        }
}

// ---------------- RMSNorm + 2D RoPE epilogue (V written transposed) ----------------
__global__ __launch_bounds__(256)
void qkv_epilogue(const float* __restrict__ qkv,
                  const float* __restrict__ qg, const float* __restrict__ kg,
                  const int* __restrict__ pos,
                  float* __restrict__ q, float* __restrict__ k, float* __restrict__ vt)
{
    const int w     = (blockIdx.x * blockDim.x + threadIdx.x) >> 5;
    const int lane  = threadIdx.x & 31;
    const int token = w >> 5;
    const int row   = w & 31;
    const int b     = token >> 10;
    const int s     = token & 1023;

    const float* src;
    float* dst = nullptr;
    float* vdst = nullptr;
    const float* gamma = nullptr;
    bool rope = true;
    if (row < 16) {
        src = qkv + (size_t)token * 2048 + row * 64;
        dst = q + ((size_t)(b * NH + row) * SS_ + s) * HD;
        gamma = qg;
    } else if (row < 24) {
        const int h = row - 16;
        src = qkv + (size_t)token * 2048 + 1024 + h * 64;
        dst = k + ((size_t)(b * NKH + h) * SS_ + s) * HD;
        gamma = kg;
    } else {
        const int h = row - 24;
        src = qkv + (size_t)token * 2048 + 1536 + h * 64;
        vdst = vt + ((size_t)(b * NKH + h) * HD) * SS_ + s;
        rope = false;
    }

    float x0 = src[lane];
    float x1 = src[lane + 32];
    float ssum = x0 * x0 + x1 * x1;
#pragma unroll
    for (int off = 16; off; off >>= 1)
        ssum += __shfl_xor_sync(0xffffffffu, ssum, off);
    const float r = rsqrtf(ssum * (1.0f / 64.0f) + 1e-6f);
    x0 *= r; x1 *= r;
    if (gamma) {
        x0 *= 1.0f + gamma[lane];
        x1 *= 1.0f + gamma[lane + 32];
    }
    if (rope) {
        const float px = (float)pos[token * 2 + 0];
        const float py = (float)pos[token * 2 + 1];
        const int j = lane & 15;
        const float invf = exp2f(-13.2877123795494f * (float)j * (1.0f / 16.0f));
        float s0, c0, s1, c1;
        sincosf(px * invf, &s0, &c0);
        sincosf(py * invf, &s1, &c1);
        const float p0 = __shfl_xor_sync(0xffffffffu, x0, 16);
        const float p1 = __shfl_xor_sync(0xffffffffu, x1, 16);
        if (lane < 16) { x0 = x0 * c0 - p0 * s0; x1 = x1 * c1 - p1 * s1; }
        else           { x0 = x0 * c0 + p0 * s0; x1 = x1 * c1 + p1 * s1; }
        dst[lane]      = x0;
        dst[lane + 32] = x1;
    } else if (vdst) {
        vdst[(size_t)lane * SS_]        = x0;
        vdst[(size_t)(lane + 32) * SS_] = x1;
    } else {
        dst[lane]      = x0;
        dst[lane + 32] = x1;
    }
}

// ================= flash attention (register MMA, unchanged R3) =================
__device__ __forceinline__ void fsplit_bf16(float x, float y, unsigned& hi, unsigned& lo)
{
    __nv_bfloat162 h = __floats2bfloat162_rn(x, y);
    hi = *(unsigned*)&h;
    __nv_bfloat162 l = __floats2bfloat162_rn(x - __bfloat162float(h.x), y - __bfloat162float(h.y));
    lo = *(unsigned*)&l;
}
__device__ __forceinline__ void fsplit_f16(float x, float y, unsigned& hi, unsigned& lo)
{
    __half2 h = __floats2half2_rn(x, y);
    hi = *(unsigned*)&h;
    __half2 l = __floats2half2_rn(x - __half2float(__low2half(h)), y - __half2float(__high2half(h)));
    lo = *(unsigned*)&l;
}

__global__ __launch_bounds__(256, 1)
void flash_attn_mma(const float* __restrict__ gq, const float* __restrict__ gk,
                    const float* __restrict__ gvt, float* __restrict__ ao)
{
    const int lane = threadIdx.x & 31;
    const int w    = threadIdx.x >> 5;
    const int bh   = blockIdx.y;
    const int b    = bh >> 4;
    const int h    = bh & 15;
    const int kh   = h >> 1;
    const int q0   = blockIdx.x * 128 + w * 16;

    const int r  = lane >> 2;
    const int cq = (lane & 3) * 2;

    const float* qb = gq  + ((size_t)(b * NH  + h ) * SS_ + q0) * HD;
    const float* kb = gk  + ((size_t)(b * NKH + kh) * SS_) * HD;
    const float* vt = gvt + ((size_t)(b * NKH + kh) * HD) * SS_;

    unsigned qh[4][4], ql[4][4];
#pragma unroll
    for (int kc = 0; kc < 4; ++kc)
#pragma unroll
        for (int i = 0; i < 4; ++i) {
            const int row = r + (i & 1) * 8;
            const int col = kc * 16 + cq + (i & 2) * 4;
            float2 t = *(const float2*)(qb + (size_t)row * HD + col);
            fsplit_bf16(t.x, t.y, qh[kc][i], ql[kc][i]);
        }

    float o[8][4];
#pragma unroll
    for (int nt = 0; nt < 8; ++nt)
#pragma unroll
        for (int j = 0; j < 4; ++j) o[nt][j] = 0.f;
    float m0 = -1e30f, m1 = -1e30f, l0 = 0.f, l1 = 0.f;

    for (int kt = 0; kt < 16; ++kt) {
        const float* kp = kb + (size_t)kt * 64 * HD;

        float s[8][4];
#pragma unroll
        for (int nt = 0; nt < 8; ++nt)
#pragma unroll
            for (int j = 0; j < 4; ++j) s[nt][j] = 0.f;

#pragma unroll
        for (int kc = 0; kc < 4; ++kc) {
            unsigned kfh[8][2], kfl[8][2];
#pragma unroll
            for (int nt = 0; nt < 8; ++nt) {
                const float* rowp = kp + (size_t)(nt * 8 + r) * HD + kc * 16 + cq;
                float2 t0 = *(const float2*)rowp;
                float2 t1 = *(const float2*)(rowp + 8);
                fsplit_bf16(t0.x, t0.y, kfh[nt][0], kfl[nt][0]);
                fsplit_bf16(t1.x, t1.y, kfh[nt][1], kfl[nt][1]);
            }
#pragma unroll
            for (int nt = 0; nt < 8; ++nt) {
                mma_bf16(s[nt], qh[kc], kfh[nt]);
                mma_bf16(s[nt], qh[kc], kfl[nt]);
                mma_bf16(s[nt], ql[kc], kfh[nt]);
            }
        }

        float mx0 = s[0][0], mx1 = s[0][2];
#pragma unroll
        for (int nt = 0; nt < 8; ++nt) {
            mx0 = fmaxf(mx0, fmaxf(s[nt][0], s[nt][1]));
            mx1 = fmaxf(mx1, fmaxf(s[nt][2], s[nt][3]));
        }
        mx0 = fmaxf(mx0, __shfl_xor_sync(0xffffffffu, mx0, 1));
        mx0 = fmaxf(mx0, __shfl_xor_sync(0xffffffffu, mx0, 2));
        mx1 = fmaxf(mx1, __shfl_xor_sync(0xffffffffu, mx1, 1));
        mx1 = fmaxf(mx1, __shfl_xor_sync(0xffffffffu, mx1, 2));

        const float mn0 = fmaxf(m0, mx0);
        const float mn1 = fmaxf(m1, mx1);
        const float al0 = __expf(m0 - mn0);
        const float al1 = __expf(m1 - mn1);
        m0 = mn0; m1 = mn1;

        float rs0 = 0.f, rs1 = 0.f;
#pragma unroll
        for (int nt = 0; nt < 8; ++nt) {
            s[nt][0] = __expf(s[nt][0] - mn0);
            s[nt][1] = __expf(s[nt][1] - mn0);
            s[nt][2] = __expf(s[nt][2] - mn1);
            s[nt][3] = __expf(s[nt][3] - mn1);
            rs0 += s[nt][0] + s[nt][1];
            rs1 += s[nt][2] + s[nt][3];
        }
        rs0 += __shfl_xor_sync(0xffffffffu, rs0, 1);
        rs0 += __shfl_xor_sync(0xffffffffu, rs0, 2);
        rs1 += __shfl_xor_sync(0xffffffffu, rs1, 1);
        rs1 += __shfl_xor_sync(0xffffffffu, rs1, 2);
        l0 = l0 * al0 + rs0;
        l1 = l1 * al1 + rs1;

#pragma unroll
        for (int nt = 0; nt < 8; ++nt) {
            o[nt][0] *= al0; o[nt][1] *= al0;
            o[nt][2] *= al1; o[nt][3] *= al1;
        }

#pragma unroll
        for (int kc = 0; kc < 4; ++kc) {
            unsigned pa[4];
            {
                __half2 t;
                t = __floats2half2_rn(s[2 * kc][0],     s[2 * kc][1]);     pa[0] = *(unsigned*)&t;
                t = __floats2half2_rn(s[2 * kc][2],     s[2 * kc][3]);     pa[1] = *(unsigned*)&t;
                t = __floats2half2_rn(s[2 * kc + 1][0], s[2 * kc + 1][1]); pa[2] = *(unsigned*)&t;
                t = __floats2half2_rn(s[2 * kc + 1][2], s[2 * kc + 1][3]); pa[3] = *(unsigned*)&t;
            }
#pragma unroll
            for (int ntd = 0; ntd < 8; ++ntd) {
                const float* vp = vt + (size_t)(ntd * 8 + r) * SS_ + kt * 64 + kc * 16 + cq;
                float2 v0 = *(const float2*)vp;
                float2 v1 = *(const float2*)(vp + 8);
                unsigned vh[2], vl[2];
                fsplit_f16(v0.x, v0.y, vh[0], vl[0]);
                fsplit_f16(v1.x, v1.y, vh[1], vl[1]);
                mma_f16r(o[ntd], pa, vh);
                mma_f16r(o[ntd], pa, vl);
            }
        }
    }

    const float inv0 = 1.0f / l0;
    const float inv1 = 1.0f / l1;
    const int sg0 = q0 + r;
    const int sg1 = q0 + r + 8;
    float* a0 = ao + (((size_t)b * SS_ + sg0) * NH + h) * HD;
    float* a1 = ao + (((size_t)b * SS_ + sg1) * NH + h) * HD;
#pragma unroll
    for (int ntd = 0; ntd < 8; ++ntd) {
        *(float2*)(a0 + ntd * 8 + cq) = make_float2(o[ntd][0] * inv0, o[ntd][1] * inv0);
        *(float2*)(a1 + ntd * 8 + cq) = make_float2(o[ntd][2] * inv1, o[ntd][3] * inv1);
    }
}

// ---------------- launch ----------------
extern "C" void kernel_launch(void* const* d_in, const int* in_sizes, int n_in,
                              void* d_out, int out_size)
{
    (void)in_sizes; (void)n_in; (void)out_size;
    const float* hidden = (const float*)d_in[0];
    const float* Wq     = (const float*)d_in[1];
    const float* Wk     = (const float*)d_in[2];
    const float* Wv     = (const float*)d_in[3];
    const float* Wo     = (const float*)d_in[4];
    const float* qg     = (const float*)d_in[5];
    const float* kg     = (const float*)d_in[6];
    const int*   pos    = (const int*)d_in[7];
    float* out = (float*)d_out;

    float *qkv, *q, *k, *vt, *ao;
    __nv_bfloat16 *ah, *al, *wth, *wtl, *oth, *otl, *aoh, *aol;
    cudaGetSymbolAddress((void**)&qkv, g_qkv);
    cudaGetSymbolAddress((void**)&q,   g_q);
    cudaGetSymbolAddress((void**)&k,   g_k);
    cudaGetSymbolAddress((void**)&vt,  g_vt);
    cudaGetSymbolAddress((void**)&ao,  g_ao);
    cudaGetSymbolAddress((void**)&ah,  g_ah);
    cudaGetSymbolAddress((void**)&al,  g_al);
    cudaGetSymbolAddress((void**)&wth, g_wth);
    cudaGetSymbolAddress((void**)&wtl, g_wtl);
    cudaGetSymbolAddress((void**)&oth, g_oth);
    cudaGetSymbolAddress((void**)&otl, g_otl);
    cudaGetSymbolAddress((void**)&aoh, g_aoh);
    cudaGetSymbolAddress((void**)&aol, g_aol);

    cudaFuncSetAttribute(gemm_presplit, cudaFuncAttributeMaxDynamicSharedMemorySize, GEMM_SMEM);

    const dim3 blk(256);

    // one-time splits
    convert_split<<<TOKENS * 1024 / 4 / 256, blk>>>(hidden, ah, al, TOKENS * 1024 / 4);
    transpose_split<<<dim3(32, 32), blk>>>(Wq, wth,               wtl,               1024);
    transpose_split<<<dim3(16, 32), blk>>>(Wk, wth + 1024 * 1024, wtl + 1024 * 1024, 512);
    transpose_split<<<dim3(16, 32), blk>>>(Wv, wth + 1536 * 1024, wtl + 1536 * 1024, 512);
    transpose_split<<<dim3(32, 32), blk>>>(Wo, oth,               otl,               1024);

    // fused QKV GEMM: [4096, 2048]
    gemm_presplit<<<dim3(16, 32), blk, GEMM_SMEM>>>(ah, al, wth, wtl, qkv, 2048);

    // RMSNorm + RoPE + transpose
    qkv_epilogue<<<TOKENS * 32 / 8, blk>>>(qkv, qg, kg, pos, q, k, vt);

    // attention
    flash_attn_mma<<<dim3(SS_ / 128, BB * NH), blk>>>(q, k, vt, ao);

    // O projection
    convert_split<<<TOKENS * 1024 / 4 / 256, blk>>>(ao, aoh, aol, TOKENS * 1024 / 4);
    gemm_presplit<<<dim3(8, 32), blk, GEMM_SMEM>>>(aoh, aol, oth, otl, out, 1024);
}